// round 1
// baseline (speedup 1.0000x reference)
#include <cuda_runtime.h>
#include <cstdint>

// Problem constants (fixed by setup_inputs: N=32768, D=512, F=64)
#define D_DIM 512
#define F_DIM 64
#define BN    64     // rows per CTA in main kernel
#define TNR   4      // rows per thread
#define KT    64     // k-chunk of M staged in smem
#define NTH   128    // threads in main kernel = (BN/TNR)*8

// Scratch (device globals: allocation-free rule)
__device__ float g_M[D_DIM * F_DIM];  // M[d][f] = V1[f][d] + sum_e W[f][d][e]*x2[e]
__device__ float g_c[F_DIM];          // c[f] = V2[f]·x2 + b[f]

// ---------------------------------------------------------------------------
// helpers
// ---------------------------------------------------------------------------
__device__ __forceinline__ unsigned smem_u32(const void* p) {
    return (unsigned)__cvta_generic_to_shared(p);
}
__device__ __forceinline__ void cp_async16(unsigned saddr, const void* g) {
    asm volatile("cp.async.cg.shared.global [%0], [%1], 16;\n" :: "r"(saddr), "l"(g));
}
#define CP_COMMIT() asm volatile("cp.async.commit_group;\n")
#define CP_WAIT(n)  asm volatile("cp.async.wait_group %0;\n" :: "n"(n))

// Packed fp32x2 FMA (sm_100+): d = a*b + d  (elementwise on 2 floats)
__device__ __forceinline__ void ffma2(float2& d, const float2& a, const float2& b) {
    asm("fma.rn.f32x2 %0, %1, %2, %0;"
        : "+l"(reinterpret_cast<unsigned long long&>(d))
        : "l"(reinterpret_cast<const unsigned long long&>(a)),
          "l"(reinterpret_cast<const unsigned long long&>(b)));
}

// ---------------------------------------------------------------------------
// Kernel A: stream W once -> build M[d][f]; also c[f]
// grid: 4096 blocks for M (8 warps -> 8 (f,d) rows each) + 1 block for c
// ---------------------------------------------------------------------------
__global__ void __launch_bounds__(256) prep_kernel(
    const float* __restrict__ x2, const float* __restrict__ V,
    const float* __restrict__ W, const float* __restrict__ b)
{
    __shared__ float s_x2[D_DIM];
    int tid = threadIdx.x;
    for (int i = tid; i < D_DIM; i += blockDim.x) s_x2[i] = x2[i];
    __syncthreads();

    int lane = tid & 31;
    int warp = tid >> 5;
    const float4* x2v = reinterpret_cast<const float4*>(s_x2);

    if (blockIdx.x < 4096) {
        // one warp per (f,d) row of W: 512-contiguous dot with x2
        int r = blockIdx.x * 8 + warp;      // 0..32767
        int f = r >> 9;
        int d = r & 511;
        const float4* wrow =
            reinterpret_cast<const float4*>(W + ((size_t)f * D_DIM + d) * D_DIM);
        float acc = 0.f;
        #pragma unroll
        for (int it = 0; it < 4; it++) {
            float4 wv = wrow[lane + it * 32];
            float4 xv = x2v[lane + it * 32];
            acc += wv.x * xv.x + wv.y * xv.y + wv.z * xv.z + wv.w * xv.w;
        }
        #pragma unroll
        for (int o = 16; o; o >>= 1) acc += __shfl_xor_sync(0xffffffffu, acc, o);
        if (lane == 0)
            g_M[d * F_DIM + f] = acc + V[(size_t)f * (2 * D_DIM) + d];
    } else {
        // c[f] = V2[f]·x2 + b[f] ; 8 warps x 8 f each
        #pragma unroll
        for (int j = 0; j < 8; j++) {
            int f = warp + j * 8;
            const float4* vrow =
                reinterpret_cast<const float4*>(V + (size_t)f * (2 * D_DIM) + D_DIM);
            float acc = 0.f;
            #pragma unroll
            for (int it = 0; it < 4; it++) {
                float4 vv = vrow[lane + it * 32];
                float4 xv = x2v[lane + it * 32];
                acc += vv.x * xv.x + vv.y * xv.y + vv.z * xv.z + vv.w * xv.w;
            }
            #pragma unroll
            for (int o = 16; o; o >>= 1) acc += __shfl_xor_sync(0xffffffffu, acc, o);
            if (lane == 0) g_c[f] = acc + b[f];
        }
    }
}

// ---------------------------------------------------------------------------
// Kernel B: fm = x1 @ M (+c), then L1-normalize/relu/@U, fused.
// CTA: 64 rows x all 64 f cols, 128 threads. Thread: 4 rows x 8 f (as 4 float2).
// M chunks (64 k x 64 f = 16KB) double-buffered via cp.async.
// x1 a-frags loaded directly from global (8-lane dup -> coalesced), prefetch 1.
// ---------------------------------------------------------------------------
__global__ void __launch_bounds__(NTH) main_kernel(
    const float* __restrict__ x1, const float* __restrict__ U,
    float* __restrict__ out)
{
    __shared__ float sM[2][KT][F_DIM];   // 32 KB
    __shared__ float sU[F_DIM];
    __shared__ float sc[F_DIM];

    int tid = threadIdx.x;
    if (tid < F_DIM) { sU[tid] = U[tid]; sc[tid] = g_c[tid]; }

    int fc = tid & 7;    // f-group 0..7  -> f = fc*8 .. fc*8+7
    int nr = tid >> 3;   // row-group 0..15 -> rows nr + 16*i
    int base = blockIdx.x * BN;
    const float* x1b = x1 + (size_t)base * D_DIM;

    // chunk loader: 16KB = 1024 float4, 8 per thread, lanes contiguous
    auto load_chunk = [&](int kt, int bi) {
        const float4* src = reinterpret_cast<const float4*>(g_M + kt * KT * F_DIM);
        unsigned sbase = smem_u32(&sM[bi][0][0]);
        #pragma unroll
        for (int j = 0; j < 8; j++) {
            int idx = j * NTH + tid;
            cp_async16(sbase + idx * 16, src + idx);
        }
    };

    load_chunk(0, 0);
    CP_COMMIT();

    // prefetch a-frags for global k4 = 0
    float4 a_nxt[TNR];
    #pragma unroll
    for (int i = 0; i < TNR; i++)
        a_nxt[i] = *reinterpret_cast<const float4*>(x1b + (size_t)(nr + 16 * i) * D_DIM);

    float2 acc[TNR][4];
    #pragma unroll
    for (int i = 0; i < TNR; i++)
        #pragma unroll
        for (int p = 0; p < 4; p++) acc[i][p] = make_float2(0.f, 0.f);

    int buf = 0;
    for (int kt = 0; kt < D_DIM / KT; kt++) {   // 8 chunks
        if (kt < D_DIM / KT - 1) {
            load_chunk(kt + 1, buf ^ 1);
            CP_COMMIT();
            CP_WAIT(1);
        } else {
            CP_WAIT(0);
        }
        __syncthreads();

        #pragma unroll
        for (int k4 = 0; k4 < KT / 4; k4++) {   // 16
            float4 a_cur[TNR];
            #pragma unroll
            for (int i = 0; i < TNR; i++) a_cur[i] = a_nxt[i];

            int gk4 = kt * (KT / 4) + k4 + 1;
            if (gk4 < D_DIM / 4) {
                #pragma unroll
                for (int i = 0; i < TNR; i++)
                    a_nxt[i] = *reinterpret_cast<const float4*>(
                        x1b + (size_t)(nr + 16 * i) * D_DIM + gk4 * 4);
            }

            #pragma unroll
            for (int j = 0; j < 4; j++) {
                int k = k4 * 4 + j;
                float4 b0 = *reinterpret_cast<const float4*>(&sM[buf][k][fc * 8]);
                float4 b1 = *reinterpret_cast<const float4*>(&sM[buf][k][fc * 8 + 4]);
                float2 bp[4] = { make_float2(b0.x, b0.y), make_float2(b0.z, b0.w),
                                 make_float2(b1.x, b1.y), make_float2(b1.z, b1.w) };
                #pragma unroll
                for (int i = 0; i < TNR; i++) {
                    float a = (j == 0) ? a_cur[i].x : (j == 1) ? a_cur[i].y
                              : (j == 2) ? a_cur[i].z : a_cur[i].w;
                    float2 av = make_float2(a, a);
                    #pragma unroll
                    for (int p = 0; p < 4; p++) ffma2(acc[i][p], av, bp[p]);
                }
            }
        }
        __syncthreads();
        buf ^= 1;
    }

    // Epilogue: per-row |fm| sum and relu(fm)*U sum, reduced over the 8 fc lanes
    #pragma unroll
    for (int i = 0; i < TNR; i++) {
        float s = 0.f, num = 0.f;
        #pragma unroll
        for (int p = 0; p < 4; p++) {
            int f = fc * 8 + 2 * p;
            float fx = acc[i][p].x + sc[f];
            float fy = acc[i][p].y + sc[f + 1];
            s   += fabsf(fx) + fabsf(fy);
            num += fmaxf(fx, 0.f) * sU[f] + fmaxf(fy, 0.f) * sU[f + 1];
        }
        #pragma unroll
        for (int o = 1; o < 8; o <<= 1) {
            s   += __shfl_xor_sync(0xffffffffu, s, o);
            num += __shfl_xor_sync(0xffffffffu, num, o);
        }
        if (fc == 0) {
            float denom = fmaxf(s, 1e-12f);
            out[base + nr + 16 * i] = num / denom;
        }
    }
}

// ---------------------------------------------------------------------------
// launch
// ---------------------------------------------------------------------------
extern "C" void kernel_launch(void* const* d_in, const int* in_sizes, int n_in,
                              void* d_out, int out_size)
{
    const float* x1 = (const float*)d_in[0];   // (N, 512)
    const float* x2 = (const float*)d_in[1];   // (1, 512)
    const float* V  = (const float*)d_in[2];   // (64, 1024)
    const float* W  = (const float*)d_in[3];   // (64, 512, 512)
    const float* b  = (const float*)d_in[4];   // (64,)
    const float* U  = (const float*)d_in[5];   // (64, 1)
    float* out = (float*)d_out;                // (N, 1)

    int N = in_sizes[0] / D_DIM;               // 32768

    prep_kernel<<<4096 + 1, 256>>>(x2, V, W, b);
    main_kernel<<<N / BN, NTH>>>(x1, U, out);
}